// round 2
// baseline (speedup 1.0000x reference)
#include <cuda_runtime.h>
#include <cuda_bf16.h>
#include <cstdint>

#define BATCH 4
#define CCH   256
#define DQK   32
#define NTOK  4096

__device__ __nv_bfloat16 g_q[BATCH * NTOK * DQK];
__device__ __nv_bfloat16 g_k[BATCH * NTOK * DQK];
__device__ __nv_bfloat16 g_v[BATCH * NTOK * CCH];

__device__ __forceinline__ uint32_t smem_u32(const void* p) {
    return (uint32_t)__cvta_generic_to_shared(p);
}
__device__ __forceinline__ void cp16(uint32_t dst, const void* src) {
    asm volatile("cp.async.cg.shared.global [%0], [%1], 16;\n" :: "r"(dst), "l"(src));
}
__device__ __forceinline__ void cp_commit() { asm volatile("cp.async.commit_group;\n"); }
template <int N> __device__ __forceinline__ void cp_wait() {
    asm volatile("cp.async.wait_group %0;\n" :: "n"(N));
}
__device__ __forceinline__ void ldsm_x4(uint32_t* r, uint32_t a) {
    asm volatile("ldmatrix.sync.aligned.m8n8.x4.shared.b16 {%0,%1,%2,%3}, [%4];\n"
                 : "=r"(r[0]), "=r"(r[1]), "=r"(r[2]), "=r"(r[3]) : "r"(a));
}
__device__ __forceinline__ void ldsm_x4_t(uint32_t* r, uint32_t a) {
    asm volatile("ldmatrix.sync.aligned.m8n8.x4.trans.shared.b16 {%0,%1,%2,%3}, [%4];\n"
                 : "=r"(r[0]), "=r"(r[1]), "=r"(r[2]), "=r"(r[3]) : "r"(a));
}
__device__ __forceinline__ void mma_bf16(float* c, const uint32_t* a, const uint32_t* b) {
    asm volatile(
        "mma.sync.aligned.m16n8k16.row.col.f32.bf16.bf16.f32 "
        "{%0,%1,%2,%3}, {%4,%5,%6,%7}, {%8,%9}, {%0,%1,%2,%3};\n"
        : "+f"(c[0]), "+f"(c[1]), "+f"(c[2]), "+f"(c[3])
        : "r"(a[0]), "r"(a[1]), "r"(a[2]), "r"(a[3]), "r"(b[0]), "r"(b[1]));
}
__device__ __forceinline__ uint32_t packbf(float a, float b) {
    __nv_bfloat162 h = __floats2bfloat162_rn(a, b);
    return reinterpret_cast<uint32_t&>(h);
}

// ===================== projection kernel =====================
#define PROJ_SMEM (32768 + 16384)

__global__ void __launch_bounds__(256, 1)
proj_kernel(const float* __restrict__ zin, const float* __restrict__ xin,
            const float* __restrict__ yin,
            const float* __restrict__ Wq, const float* __restrict__ bq,
            const float* __restrict__ Wk, const float* __restrict__ bk,
            const float* __restrict__ Wv, const float* __restrict__ bv) {
    extern __shared__ char smem[];
    char* sA = smem;            // [c=256][128B] bf16 swizzled
    char* sW = smem + 32768;    // [d=32][512B]  bf16 swizzled

    const int sel = blockIdx.z, b = blockIdx.y, n0 = blockIdx.x * 64;
    const int tid = threadIdx.x, l = tid & 31, wid = tid >> 5;
    const int wr = wid >> 1, wc = wid & 1;

    const float* src  = (sel == 0) ? xin : ((sel == 1) ? yin : zin);
    const float* W    = (sel == 0) ? Wq  : ((sel == 1) ? Wk  : Wv);
    const float* bias = (sel == 0) ? bq  : ((sel == 1) ? bk  : bv);
    __nv_bfloat16* dst = (sel == 0) ? g_q : ((sel == 1) ? g_k : g_v);
    const int dstw    = (sel == 2) ? CCH : DQK;
    const int nchunks = (sel == 2) ? 8 : 1;

#pragma unroll
    for (int j = 0; j < 16; ++j) {
        int id = j * 256 + tid;
        int c = id >> 4, nq = id & 15;
        float4 f = *(const float4*)(src + ((size_t)(b * CCH + c) * NTOK + n0 + nq * 4));
        int nb = nq * 8;
        int phys = c * 128 + ((((nb & ~15) ^ ((c & 7) << 4))) | (nb & 15));
        *(__nv_bfloat162*)(sA + phys)     = __floats2bfloat162_rn(f.x, f.y);
        *(__nv_bfloat162*)(sA + phys + 4) = __floats2bfloat162_rn(f.z, f.w);
    }

    for (int oc = 0; oc < nchunks; ++oc) {
        __syncthreads();
#pragma unroll
        for (int j = 0; j < 8; ++j) {
            int id = j * 256 + tid;
            int dd = id >> 6, cq = id & 63;
            float4 f = *(const float4*)(W + (size_t)(oc * 32 + dd) * CCH + cq * 4);
            int cb = cq * 8;
            int phys = dd * 512 + ((((cb & ~15) ^ ((dd & 7) << 4))) | (cb & 15));
            *(__nv_bfloat162*)(sW + phys)     = __floats2bfloat162_rn(f.x, f.y);
            *(__nv_bfloat162*)(sW + phys + 4) = __floats2bfloat162_rn(f.z, f.w);
        }
        __syncthreads();

        float acc[2][4] = {{0.f,0.f,0.f,0.f},{0.f,0.f,0.f,0.f}};
#pragma unroll
        for (int ks = 0; ks < 16; ++ks) {
            uint32_t aA[4], bw[4];
            int crow = ks * 16 + (l & 7) + ((l & 16) ? 8 : 0);
            int nb   = wr * 32 + ((l & 8) ? 16 : 0);
            ldsm_x4_t(aA, smem_u32(sA + crow * 128 + (nb ^ ((crow & 7) << 4))));
            int dd = wc * 16 + (l & 7) + ((l & 16) ? 8 : 0);
            int cb = ks * 32 + ((l & 8) ? 16 : 0);
            ldsm_x4(bw, smem_u32(sW + dd * 512 + (cb ^ ((dd & 7) << 4))));
            mma_bf16(acc[0], aA, bw);
            mma_bf16(acc[1], aA, bw + 2);
        }

        int nloc = wr * 16 + (l >> 2);
        int dloc = wc * 16 + 2 * (l & 3);
#pragma unroll
        for (int t = 0; t < 2; ++t) {
            int d = oc * 32 + dloc + t * 8;
            float b0 = bias[d], b1 = bias[d + 1];
            *(__nv_bfloat162*)(dst + ((size_t)(b * NTOK + n0 + nloc) * dstw + d)) =
                __floats2bfloat162_rn(acc[t][0] + b0, acc[t][1] + b1);
            *(__nv_bfloat162*)(dst + ((size_t)(b * NTOK + n0 + nloc + 8) * dstw + d)) =
                __floats2bfloat162_rn(acc[t][2] + b0, acc[t][3] + b1);
        }
    }
}

// ===================== flash attention kernel =====================
#define FLASH_SMEM (4096 + 2 * 4096 + 2 * 32768)

__device__ __forceinline__ void load_kv(char* sK, char* sV,
                                        const __nv_bfloat16* kp,
                                        const __nv_bfloat16* vp,
                                        int n0k, int tid) {
    {
        int n = tid >> 2, cc = tid & 3;
        cp16(smem_u32(sK + n * 64 + ((cc * 16) ^ (((n >> 1) & 3) << 4))),
             kp + (size_t)(n0k + n) * DQK + cc * 8);
    }
#pragma unroll
    for (int j = 0; j < 8; ++j) {
        int id = j * 256 + tid;
        int kk = id >> 5, c16 = id & 31;
        cp16(smem_u32(sV + kk * 512 + ((c16 * 16) ^ ((kk & 7) << 4))),
             vp + (size_t)(n0k + kk) * CCH + c16 * 8);
    }
}

__global__ void __launch_bounds__(256, 1)
flash_kernel(const float* __restrict__ zin, float* __restrict__ out) {
    extern __shared__ char smem[];
    char* sQ  = smem;
    char* sK0 = smem + 4096;
    char* sK1 = smem + 8192;
    char* sV0 = smem + 12288;
    char* sV1 = smem + 45056;

    const int b = blockIdx.y, m0 = blockIdx.x * 64;
    const int tid = threadIdx.x, l = tid & 31, wid = tid >> 5;
    const int wr = wid >> 1, wc = wid & 1;

    const __nv_bfloat16* qp = g_q + (size_t)b * NTOK * DQK;
    const __nv_bfloat16* kp = g_k + (size_t)b * NTOK * DQK;
    const __nv_bfloat16* vp = g_v + (size_t)b * NTOK * CCH;

    {
        int m = tid >> 2, cc = tid & 3;
        cp16(smem_u32(sQ + m * 64 + ((cc * 16) ^ (((m >> 1) & 3) << 4))),
             qp + (size_t)(m0 + m) * DQK + cc * 8);
    }
    load_kv(sK0, sV0, kp, vp, 0, tid);
    cp_commit();
    load_kv(sK1, sV1, kp, vp, 64, tid);
    cp_commit();
    cp_wait<1>();
    __syncthreads();

    uint32_t aq[2][4];
#pragma unroll
    for (int ks = 0; ks < 2; ++ks) {
        int row = wr * 16 + (l & 15);
        int cb  = ks * 32 + ((l & 16) ? 16 : 0);
        ldsm_x4(aq[ks], smem_u32(sQ + row * 64 + (cb ^ (((row >> 1) & 3) << 4))));
    }

    float o[16][4];
#pragma unroll
    for (int t = 0; t < 16; ++t) { o[t][0]=0.f; o[t][1]=0.f; o[t][2]=0.f; o[t][3]=0.f; }
    float mr0 = -1e30f, mr1 = -1e30f, li0 = 0.f, li1 = 0.f;

#pragma unroll 1
    for (int it = 0; it < 64; ++it) {
        char* cK = (it & 1) ? sK1 : sK0;
        char* cV = (it & 1) ? sV1 : sV0;

        float s[8][4];
#pragma unroll
        for (int nt = 0; nt < 8; ++nt) {
            s[nt][0]=0.f; s[nt][1]=0.f; s[nt][2]=0.f; s[nt][3]=0.f;
            uint32_t bk[4];
            int n  = nt * 8 + (l & 7);
            int cb = (l >> 3) << 4;
            ldsm_x4(bk, smem_u32(cK + n * 64 + (cb ^ (((n >> 1) & 3) << 4))));
            mma_bf16(s[nt], aq[0], bk);
            mma_bf16(s[nt], aq[1], bk + 2);
        }

        float tm0 = -1e30f, tm1 = -1e30f;
#pragma unroll
        for (int nt = 0; nt < 8; ++nt) {
            tm0 = fmaxf(tm0, fmaxf(s[nt][0], s[nt][1]));
            tm1 = fmaxf(tm1, fmaxf(s[nt][2], s[nt][3]));
        }
        tm0 = fmaxf(tm0, __shfl_xor_sync(0xffffffffu, tm0, 1));
        tm0 = fmaxf(tm0, __shfl_xor_sync(0xffffffffu, tm0, 2));
        tm1 = fmaxf(tm1, __shfl_xor_sync(0xffffffffu, tm1, 1));
        tm1 = fmaxf(tm1, __shfl_xor_sync(0xffffffffu, tm1, 2));
        float nm0 = fmaxf(mr0, tm0), nm1 = fmaxf(mr1, tm1);
        float al0 = __expf(mr0 - nm0), al1 = __expf(mr1 - nm1);
        mr0 = nm0; mr1 = nm1;

        float rs0 = 0.f, rs1 = 0.f;
#pragma unroll
        for (int nt = 0; nt < 8; ++nt) {
            s[nt][0] = __expf(s[nt][0] - nm0);
            s[nt][1] = __expf(s[nt][1] - nm0);
            s[nt][2] = __expf(s[nt][2] - nm1);
            s[nt][3] = __expf(s[nt][3] - nm1);
            rs0 += s[nt][0] + s[nt][1];
            rs1 += s[nt][2] + s[nt][3];
        }
        rs0 += __shfl_xor_sync(0xffffffffu, rs0, 1);
        rs0 += __shfl_xor_sync(0xffffffffu, rs0, 2);
        rs1 += __shfl_xor_sync(0xffffffffu, rs1, 1);
        rs1 += __shfl_xor_sync(0xffffffffu, rs1, 2);
        li0 = li0 * al0 + rs0;
        li1 = li1 * al1 + rs1;

#pragma unroll
        for (int t = 0; t < 16; ++t) {
            o[t][0] *= al0; o[t][1] *= al0;
            o[t][2] *= al1; o[t][3] *= al1;
        }

        uint32_t pA[4][4];
#pragma unroll
        for (int j = 0; j < 4; ++j) {
            pA[j][0] = packbf(s[2*j][0],   s[2*j][1]);
            pA[j][1] = packbf(s[2*j][2],   s[2*j][3]);
            pA[j][2] = packbf(s[2*j+1][0], s[2*j+1][1]);
            pA[j][3] = packbf(s[2*j+1][2], s[2*j+1][3]);
        }

#pragma unroll
        for (int j = 0; j < 4; ++j) {
#pragma unroll
            for (int np = 0; np < 8; ++np) {
                uint32_t bv[4];
                int row   = j * 16 + (l & 15);
                int cbyte = wc * 256 + np * 32 + ((l & 16) ? 16 : 0);
                ldsm_x4_t(bv, smem_u32(cV + row * 512 + (cbyte ^ ((row & 7) << 4))));
                mma_bf16(o[np * 2],     pA[j], bv);
                mma_bf16(o[np * 2 + 1], pA[j], bv + 2);
            }
        }

        __syncthreads();
        if (it + 2 < 64) load_kv(cK, cV, kp, vp, (it + 2) * 64, tid);
        cp_commit();
        cp_wait<1>();
        __syncthreads();
    }

    float inv0 = 1.f / li0, inv1 = 1.f / li1;
    int r0 = m0 + wr * 16 + (l >> 2);
#pragma unroll
    for (int nt = 0; nt < 16; ++nt) {
        int ch = wc * 128 + nt * 8 + 2 * (l & 3);
        size_t base0 = ((size_t)(b * CCH + ch)) * NTOK + r0;
        size_t base1 = base0 + NTOK;
        out[base0]     = zin[base0]     + o[nt][0] * inv0;
        out[base1]     = zin[base1]     + o[nt][1] * inv0;
        out[base0 + 8] = zin[base0 + 8] + o[nt][2] * inv1;
        out[base1 + 8] = zin[base1 + 8] + o[nt][3] * inv1;
    }
}

extern "C" void kernel_launch(void* const* d_in, const int* in_sizes, int n_in,
                              void* d_out, int out_size) {
    const float* z  = (const float*)d_in[0];
    const float* x  = (const float*)d_in[1];
    const float* y  = (const float*)d_in[2];
    const float* Wq = (const float*)d_in[3];
    const float* bq = (const float*)d_in[4];
    const float* Wk = (const float*)d_in[5];
    const float* bk = (const float*)d_in[6];
    const float* Wv = (const float*)d_in[7];
    const float* bv = (const float*)d_in[8];
    float* out = (float*)d_out;

    cudaFuncSetAttribute(flash_kernel, cudaFuncAttributeMaxDynamicSharedMemorySize,
                         FLASH_SMEM);

    proj_kernel<<<dim3(64, 4, 3), 256, PROJ_SMEM>>>(z, x, y, Wq, bq, Wk, bk, Wv, bv);
    flash_kernel<<<dim3(64, 4), 256, FLASH_SMEM>>>(z, out);
}